// round 1
// baseline (speedup 1.0000x reference)
#include <cuda_runtime.h>

// PNN_62156766707845 — GB300 sm_103a
// out[b] = MLP( first(b) + inner(b)^2 ), first/inner = (emb(b) * Xv) · W
// Strategy: FFMA2 (f32x2) packed accumulation of (first, inner) pairs,
// merged weights in SMEM, 2 threads per row (16 output dims each).

#define FDIM 39
#define EDIM 16
#define VDIM 100000
#define BROWS 112
#define NTHR  224

// SMEM float2 stride per (f,e): 18 float2 per half, 36 total (half offset 18
// -> +144B -> +4 banks vs half0 -> conflict-free dual-broadcast LDS.128)
#define FE_STRIDE2 36
#define W_F2_COUNT (FDIM * EDIM * FE_STRIDE2)       // 22464 float2 = 179712 B
#define XS_STRIDE  33
#define SMEM_BYTES (W_F2_COUNT * 8 + BROWS * XS_STRIDE * 4 + 2 * 1024 * 4 + 3 * 32 * 4 + 16)

__device__ __forceinline__ unsigned long long pk2(float a, float b) {
    unsigned long long r;
    asm("mov.b64 %0, {%1, %2};" : "=l"(r) : "f"(a), "f"(b));
    return r;
}
__device__ __forceinline__ void unpk2(unsigned long long v, float& lo, float& hi) {
    asm("mov.b64 {%0, %1}, %2;" : "=f"(lo), "=f"(hi) : "l"(v));
}
__device__ __forceinline__ void ffma2(unsigned long long& d, unsigned long long a,
                                      unsigned long long b) {
    asm("fma.rn.f32x2 %0, %1, %2, %3;" : "=l"(d) : "l"(a), "l"(b), "l"(d));
}

extern "C" __global__ void __launch_bounds__(NTHR, 1)
pnn_kernel(const int* __restrict__ Xi, const float* __restrict__ Xv,
           const float* __restrict__ emb,
           const float* __restrict__ w_first, const float* __restrict__ w_inner,
           const float* __restrict__ lin1W, const float* __restrict__ lin1b,
           const float* __restrict__ lin2W, const float* __restrict__ lin2b,
           const float* __restrict__ lastW, const float* __restrict__ lastb,
           float* __restrict__ out, int B)
{
    extern __shared__ char smem[];
    float2* Wsm = (float2*)smem;
    float*  xs  = (float*)(smem + W_F2_COUNT * 8);
    float*  l1  = xs + BROWS * XS_STRIDE;
    float*  l2  = l1 + 1024;
    float*  bb1 = l2 + 1024;
    float*  bb2 = bb1 + 32;
    float*  lw  = bb2 + 32;
    float*  lb  = lw + 32;

    const int tid = threadIdx.x;

    // ---- stage weights: merged (w_first[d], w_inner[d]) pairs ----
    for (int i = tid; i < FDIM * EDIM * 32; i += NTHR) {
        int d  = i & 31;
        int fe = i >> 5;
        int f  = fe >> 4;
        int e  = fe & 15;
        float wf = w_first[(d * FDIM + f) * EDIM + e];
        float wi = w_inner[(d * FDIM + f) * EDIM + e];
        int half = d >> 4, dl = d & 15;
        Wsm[fe * FE_STRIDE2 + half * 18 + dl] = make_float2(wf, wi);
    }
    for (int i = tid; i < 1024; i += NTHR) { l1[i] = lin1W[i]; l2[i] = lin2W[i]; }
    if (tid < 32) { bb1[tid] = lin1b[tid]; bb2[tid] = lin2b[tid]; lw[tid] = lastW[tid]; }
    if (tid == 0) lb[0] = lastb[0];
    __syncthreads();

    const int row  = blockIdx.x * BROWS + (tid >> 1);
    const int half = tid & 1;
    const int rowc = (row < B) ? row : (B - 1);
    const long long base = (long long)rowc * FDIM;

    unsigned long long acc[16];
#pragma unroll
    for (int i = 0; i < 16; i++) acc[i] = 0ULL;

    const float4* tab = (const float4*)emb;

    // prefetch: f=0 row, f=1 index
    int   idxN = Xi[base];
    float xvN  = Xv[base];
    const float4* p0 = tab + ((long long)idxN) * 4;    // f=0 offset
    float4 b0 = p0[0], b1v = p0[1], b2v = p0[2], b3v = p0[3];
    float  scN = xvN;
    idxN = Xi[base + 1];
    xvN  = Xv[base + 1];

    for (int f = 0; f < FDIM; f++) {
        float4 r0 = b0, r1 = b1v, r2 = b2v, r3 = b3v;
        float  s  = scN;
        if (f < FDIM - 1) {
            const float4* p = tab + ((long long)(f + 1) * VDIM + idxN) * 4;
            b0 = p[0]; b1v = p[1]; b2v = p[2]; b3v = p[3];
            scN = xvN;
            if (f < FDIM - 2) {
                idxN = Xi[base + f + 2];
                xvN  = Xv[base + f + 2];
            }
        }
        float v[16];
        v[0]  = r0.x * s; v[1]  = r0.y * s; v[2]  = r0.z * s; v[3]  = r0.w * s;
        v[4]  = r1.x * s; v[5]  = r1.y * s; v[6]  = r1.z * s; v[7]  = r1.w * s;
        v[8]  = r2.x * s; v[9]  = r2.y * s; v[10] = r2.z * s; v[11] = r2.w * s;
        v[12] = r3.x * s; v[13] = r3.y * s; v[14] = r3.z * s; v[15] = r3.w * s;

        const float2* wr = Wsm + f * (EDIM * FE_STRIDE2) + half * 18;
#pragma unroll
        for (int e = 0; e < 16; e++) {
            unsigned long long vv = pk2(v[e], v[e]);
            const float2* we = wr + e * FE_STRIDE2;
#pragma unroll
            for (int p4 = 0; p4 < 8; p4++) {
                ulonglong2 w = *reinterpret_cast<const ulonglong2*>(we + p4 * 2);
                ffma2(acc[2 * p4],     vv, w.x);
                ffma2(acc[2 * p4 + 1], vv, w.y);
            }
        }
    }

    // ---- epilogue: x = first + inner^2, then 32->32->32->1 MLP ----
    const int rl = tid >> 1;
    float* xr = xs + rl * XS_STRIDE;

#pragma unroll
    for (int i = 0; i < 16; i++) {
        float fo, so;
        unpk2(acc[i], fo, so);
        xr[half * 16 + i] = fo + so * so;
    }
    __syncwarp();

    float h[16];
#pragma unroll
    for (int jl = 0; jl < 16; jl++) {
        int j = half * 16 + jl;
        float a = bb1[j];
#pragma unroll
        for (int d = 0; d < 32; d++) a = fmaf(l1[j * 32 + d], xr[d], a);
        h[jl] = fmaxf(a, 0.0f);
    }
    __syncwarp();
#pragma unroll
    for (int jl = 0; jl < 16; jl++) xr[half * 16 + jl] = h[jl];
    __syncwarp();

#pragma unroll
    for (int jl = 0; jl < 16; jl++) {
        int j = half * 16 + jl;
        float a = bb2[j];
#pragma unroll
        for (int d = 0; d < 32; d++) a = fmaf(l2[j * 32 + d], xr[d], a);
        h[jl] = fmaxf(a, 0.0f);
    }
    __syncwarp();
#pragma unroll
    for (int jl = 0; jl < 16; jl++) xr[half * 16 + jl] = h[jl];
    __syncwarp();

    if (half == 0 && row < B) {
        float a = lb[0];
#pragma unroll
        for (int j = 0; j < 32; j++) a = fmaf(lw[j], xr[j], a);
        out[row] = a;
    }
}

extern "C" void kernel_launch(void* const* d_in, const int* in_sizes, int n_in,
                              void* d_out, int out_size)
{
    const int*   Xi      = (const int*)d_in[0];
    const float* Xv      = (const float*)d_in[1];
    const float* emb     = (const float*)d_in[2];
    const float* w_first = (const float*)d_in[3];
    const float* w_inner = (const float*)d_in[4];
    const float* lin1W   = (const float*)d_in[5];
    const float* lin1b   = (const float*)d_in[6];
    const float* lin2W   = (const float*)d_in[7];
    const float* lin2b   = (const float*)d_in[8];
    const float* lastW   = (const float*)d_in[9];
    const float* lastb   = (const float*)d_in[10];
    float* out = (float*)d_out;

    const int B = in_sizes[0] / FDIM;

    cudaFuncSetAttribute(pnn_kernel, cudaFuncAttributeMaxDynamicSharedMemorySize,
                         SMEM_BYTES);

    const int grid = (B + BROWS - 1) / BROWS;
    pnn_kernel<<<grid, NTHR, SMEM_BYTES>>>(Xi, Xv, emb, w_first, w_inner,
                                           lin1W, lin1b, lin2W, lin2b,
                                           lastW, lastb, out, B);
}